// round 1
// baseline (speedup 1.0000x reference)
#include <cuda_runtime.h>
#include <cuda_bf16.h>
#include <stdint.h>

#define EPS 1e-8f

static const int BATCH = 64;
static const int N_OBS = 2048;
static const int HIST  = 512;

// Per-observation normalization params: {mean_merged, inv_std} ({0,1} if total<2)
__device__ float2 g_params[N_OBS];

// ---------------------------------------------------------------------------
// Kernel 1: per-observation batch stats + Welford merge -> g_params
// One thread per observation n. 2048 threads total.
// ---------------------------------------------------------------------------
__global__ void sig_stats_kernel(const float* __restrict__ values,
                                 const float* __restrict__ means,
                                 const float* __restrict__ M2s,
                                 const int*   __restrict__ counts,
                                 const int*   __restrict__ sig_ids)
{
    int n = blockIdx.x * blockDim.x + threadIdx.x;
    if (n >= N_OBS) return;

    // Gather the 64 last-timestep values for this observation.
    const size_t obs_stride = (size_t)N_OBS * HIST;   // elements between batch rows
    const float* base = values + (size_t)n * HIST + (HIST - 1);

    float v[BATCH];
    float sum = 0.f;
#pragma unroll
    for (int b = 0; b < BATCH; b++) {
        v[b] = __ldg(base + (size_t)b * obs_stride);
        sum += v[b];
    }
    float mean_new = sum * (1.0f / BATCH);

    float ss = 0.f;
#pragma unroll
    for (int b = 0; b < BATCH; b++) {
        float d = v[b] - mean_new;
        ss += d * d;
    }
    // jnp.var -> mean of squared deviations; M2_new = var_new * count_new = ss
    float M2_new = ss;
    float count_new = (float)BATCH;

    int   sig = sig_ids[n];
    float c   = (float)counts[sig];
    float m   = means[sig];
    float M2  = M2s[sig];

    float delta = mean_new - m;
    float total = c + count_new;
    float m_merged  = m + delta * (count_new / total);
    float M2_merged = M2 + M2_new + delta * delta * c * count_new / total;

    float var = M2_merged / total;
    float inv_std = rsqrtf(var + EPS);

    float2 p;
    if (total >= 2.0f) {
        p.x = m_merged;
        p.y = inv_std;
    } else {
        p.x = 0.0f;   // out = (v - 0) * 1 = v
        p.y = 1.0f;
    }
    g_params[n] = p;
}

// ---------------------------------------------------------------------------
// Kernel 2: streaming normalize. float4 vectors; n = (vec >> 7) & 2047.
// hist/4 = 128 = 2^7 float4 per (b, n) row; N_OBS = 2048 = 2^11.
// ---------------------------------------------------------------------------
__global__ void sig_norm_kernel(const float4* __restrict__ values,
                                float4* __restrict__ out,
                                int64_t n_vec)
{
    int64_t i = (int64_t)blockIdx.x * blockDim.x + threadIdx.x;
    if (i >= n_vec) return;

    int n = (int)((i >> 7) & (N_OBS - 1));
    float2 p = g_params[n];

    float4 v = values[i];
    float4 o;
    o.x = (v.x - p.x) * p.y;
    o.y = (v.y - p.x) * p.y;
    o.z = (v.z - p.x) * p.y;
    o.w = (v.w - p.x) * p.y;
    out[i] = o;
}

extern "C" void kernel_launch(void* const* d_in, const int* in_sizes, int n_in,
                              void* d_out, int out_size)
{
    const float* values  = (const float*)d_in[0];
    const float* means   = (const float*)d_in[1];
    const float* M2s     = (const float*)d_in[2];
    const int*   counts  = (const int*)d_in[3];
    const int*   sig_ids = (const int*)d_in[4];
    float* out = (float*)d_out;

    // Kernel 1: one thread per observation
    {
        int threads = 256;
        int blocks = (N_OBS + threads - 1) / threads;
        sig_stats_kernel<<<blocks, threads>>>(values, means, M2s, counts, sig_ids);
    }

    // Kernel 2: streaming normalize, one float4 per thread
    {
        int64_t n_vec = (int64_t)BATCH * N_OBS * HIST / 4;   // 16,777,216
        int threads = 256;
        int64_t blocks = (n_vec + threads - 1) / threads;    // 65,536
        sig_norm_kernel<<<(unsigned)blocks, threads>>>(
            (const float4*)values, (float4*)out, n_vec);
    }
}

// round 2
// speedup vs baseline: 1.1272x; 1.1272x over previous
#include <cuda_runtime.h>
#include <cuda_bf16.h>
#include <stdint.h>

#define EPS 1e-8f

static const int BATCH = 64;
static const int N_OBS = 2048;
static const int HIST  = 512;

// Per-observation normalization params: {mean_merged, inv_std} ({0,1} if total<2)
__device__ float2 g_params[N_OBS];

// ---------------------------------------------------------------------------
// Kernel 1: per-observation batch stats + Welford merge -> g_params
// One warp per observation. Thread t loads batch rows t and t+32.
// Single-pass: var = E[v^2] - mean^2.
// ---------------------------------------------------------------------------
__global__ void sig_stats_kernel(const float* __restrict__ values,
                                 const float* __restrict__ means,
                                 const float* __restrict__ M2s,
                                 const int*   __restrict__ counts,
                                 const int*   __restrict__ sig_ids)
{
    int n = blockIdx.x;                 // observation index, 2048 blocks
    int t = threadIdx.x;                // 0..31

    const size_t obs_stride = (size_t)N_OBS * HIST;     // elements between batch rows
    const float* base = values + (size_t)n * HIST + (HIST - 1);

    float v0 = __ldg(base + (size_t)t        * obs_stride);
    float v1 = __ldg(base + (size_t)(t + 32) * obs_stride);

    float s  = v0 + v1;
    float sq = v0 * v0 + v1 * v1;

#pragma unroll
    for (int off = 16; off > 0; off >>= 1) {
        s  += __shfl_xor_sync(0xFFFFFFFFu, s,  off);
        sq += __shfl_xor_sync(0xFFFFFFFFu, sq, off);
    }

    if (t == 0) {
        float mean_new = s * (1.0f / BATCH);
        float var_new  = sq * (1.0f / BATCH) - mean_new * mean_new;
        float M2_new   = var_new * (float)BATCH;
        float count_new = (float)BATCH;

        int   sig = sig_ids[n];
        float c   = (float)counts[sig];
        float m   = means[sig];
        float M2  = M2s[sig];

        float delta = mean_new - m;
        float total = c + count_new;
        float m_merged  = m + delta * (count_new / total);
        float M2_merged = M2 + M2_new + delta * delta * c * count_new / total;

        float var = M2_merged / total;
        float inv_std = rsqrtf(var + EPS);

        float2 p;
        if (total >= 2.0f) {
            p.x = m_merged;
            p.y = inv_std;
        } else {
            p.x = 0.0f;   // out = (v - 0) * 1 = v
            p.y = 1.0f;
        }
        g_params[n] = p;
    }
}

// ---------------------------------------------------------------------------
// Kernel 2: streaming normalize. 2 float4 vectors per thread, front-batched.
// hist/4 = 128 = 2^7 float4 per (b, n) row; N_OBS = 2048 = 2^11.
// 32-bit indexing: n_vec = 16,777,216 < 2^31.
// ---------------------------------------------------------------------------
__global__ void sig_norm_kernel(const float4* __restrict__ values,
                                float4* __restrict__ out)
{
    // Each block handles 256 threads * 2 vec = 512 consecutive float4.
    unsigned i0 = blockIdx.x * 512u + threadIdx.x;
    unsigned i1 = i0 + 256u;

    // Front-batch both loads (MLP=2)
    float4 v0 = __ldcs(&values[i0]);
    float4 v1 = __ldcs(&values[i1]);

    unsigned n0 = (i0 >> 7) & (N_OBS - 1);
    unsigned n1 = (i1 >> 7) & (N_OBS - 1);
    float2 p0 = g_params[n0];
    float2 p1 = g_params[n1];

    float4 o0, o1;
    o0.x = (v0.x - p0.x) * p0.y;
    o0.y = (v0.y - p0.x) * p0.y;
    o0.z = (v0.z - p0.x) * p0.y;
    o0.w = (v0.w - p0.x) * p0.y;
    o1.x = (v1.x - p1.x) * p1.y;
    o1.y = (v1.y - p1.x) * p1.y;
    o1.z = (v1.z - p1.x) * p1.y;
    o1.w = (v1.w - p1.x) * p1.y;

    __stcs(&out[i0], o0);
    __stcs(&out[i1], o1);
}

extern "C" void kernel_launch(void* const* d_in, const int* in_sizes, int n_in,
                              void* d_out, int out_size)
{
    const float* values  = (const float*)d_in[0];
    const float* means   = (const float*)d_in[1];
    const float* M2s     = (const float*)d_in[2];
    const int*   counts  = (const int*)d_in[3];
    const int*   sig_ids = (const int*)d_in[4];
    float* out = (float*)d_out;

    // Kernel 1: one warp per observation
    sig_stats_kernel<<<N_OBS, 32>>>(values, means, M2s, counts, sig_ids);

    // Kernel 2: streaming normalize, 2 float4 per thread
    {
        unsigned n_vec = (unsigned)((int64_t)BATCH * N_OBS * HIST / 4); // 16,777,216
        unsigned blocks = n_vec / 512u;                                 // 32,768
        sig_norm_kernel<<<blocks, 256>>>((const float4*)values, (float4*)out);
    }
}